// round 6
// baseline (speedup 1.0000x reference)
#include <cuda_runtime.h>
#include <cstdint>

// Problem constants (fixed by the dataset)
#define NMAX 100000
#define EMAX 1600000
#define HID  64

// ---------------- device scratch (no allocations allowed) ----------------
__device__ int   g_cnt[NMAX];
__device__ float g_dinv[NMAX];
__device__ int   g_rowptr[NMAX + 1];
__device__ int   g_woff[NMAX];
__device__ int   g_bsum[512];
__device__ int   g_boff[512];
__device__ int   g_csr_src[EMAX + NMAX];
__device__ float g_H [(size_t)NMAX * HID];
__device__ float g_Xa[(size_t)NMAX * HID];
__device__ float g_Xb[(size_t)NMAX * HID];

// ---------------- packed fp32x2 helpers (Blackwell f32x2 pipe) ----------------
__device__ __forceinline__ void ffma2(unsigned long long& d,
                                      unsigned long long a,
                                      unsigned long long b) {
    asm("fma.rn.f32x2 %0, %1, %2, %3;" : "=l"(d) : "l"(a), "l"(b), "l"(d));
}
__device__ __forceinline__ float2 unpack2(unsigned long long v) {
    float2 f;
    asm("mov.b64 {%0, %1}, %2;" : "=f"(f.x), "=f"(f.y) : "l"(v));
    return f;
}

// ---------------- graph build ----------------
__global__ void k_init_cnt(int n) {
    int i = blockIdx.x * blockDim.x + threadIdx.x;
    if (i < n) g_cnt[i] = 1;   // self-loop
}

__global__ void k_count(const int* __restrict__ dst, int e) {
    int i = blockIdx.x * blockDim.x + threadIdx.x;
    if (i < e) atomicAdd(&g_cnt[dst[i]], 1);
}

__global__ void k_blocksum(int n) {
    __shared__ int sh[256];
    int i = blockIdx.x * 256 + threadIdx.x;
    sh[threadIdx.x] = (i < n) ? g_cnt[i] : 0;
    __syncthreads();
    for (int off = 128; off; off >>= 1) {
        if (threadIdx.x < off) sh[threadIdx.x] += sh[threadIdx.x + off];
        __syncthreads();
    }
    if (threadIdx.x == 0) g_bsum[blockIdx.x] = sh[0];
}

// single block, 512 threads: exclusive scan of block sums
__global__ void k_topscan(int nblk) {
    __shared__ int sh[512];
    int t = threadIdx.x;
    int v = (t < nblk) ? g_bsum[t] : 0;
    sh[t] = v;
    for (int off = 1; off < 512; off <<= 1) {
        __syncthreads();
        int x = (t >= off) ? sh[t - off] : 0;
        __syncthreads();
        sh[t] += x;
    }
    __syncthreads();
    if (t < nblk) g_boff[t] = sh[t] - v;   // exclusive
}

__global__ void k_scanwrite(int n) {
    __shared__ int sh[256];
    int t = threadIdx.x;
    int i = blockIdx.x * 256 + t;
    int v = (i < n) ? g_cnt[i] : 0;
    sh[t] = v;
    for (int off = 1; off < 256; off <<= 1) {
        __syncthreads();
        int x = (t >= off) ? sh[t - off] : 0;
        __syncthreads();
        sh[t] += x;
    }
    __syncthreads();
    int excl = sh[t] - v;
    if (i < n) {
        int rp = g_boff[blockIdx.x] + excl;
        g_rowptr[i] = rp;
        g_dinv[i] = rsqrtf((float)v);
        // self-loop edge first (deterministic slot)
        g_csr_src[rp] = i;
        g_woff[i] = rp + 1;
        if (i == n - 1) g_rowptr[n] = rp + v;
    }
}

__global__ void k_scatter(const int* __restrict__ src, const int* __restrict__ dst, int e) {
    int i = blockIdx.x * blockDim.x + threadIdx.x;
    if (i >= e) return;
    int d = dst[i];
    int pos = atomicAdd(&g_woff[d], 1);
    g_csr_src[pos] = src[i];
}

// ---------------- dense GEMM: C[r,:] = dinv[r] * (A[r,:K] @ W[K,64]) ----------------
// Inner loop uses packed fma.rn.f32x2 (2 FMAs per issue slot). A row-pairs come
// straight out of LDS.128 as aligned 64-bit packs; W tile is stored duplicated
// (w,w) in shared so no in-loop packing movs are needed.
template <int K>
__global__ void __launch_bounds__(256) k_gemm(const float* __restrict__ A,
                                              const float* __restrict__ W,
                                              float* __restrict__ Cc, int n) {
    constexpr int BM = 128, BN = 64, BK = 16;
    __shared__ __align__(16) float  As[BK][BM];
    __shared__ __align__(16) float2 Ws2[BK][BN];   // (w,w) duplicated
    int tid = threadIdx.x;
    int m0 = blockIdx.x * BM;
    int tx = tid & 15;   // cols tx*4 .. tx*4+3
    int ty = tid >> 4;   // rows ty*8 .. ty*8+7
    unsigned long long acc[4][4] = {};   // [row-pair][col], lo=even row, hi=odd row

    for (int k0 = 0; k0 < K; k0 += BK) {
        // A tile: 128x16 -> 512 float4 loads (2/thread), stored transposed
        #pragma unroll
        for (int r = 0; r < 2; ++r) {
            int q = tid + r * 256;
            int row = q >> 2;
            int c4 = (q & 3) * 4;
            int gr = m0 + row;
            float4 v = make_float4(0.f, 0.f, 0.f, 0.f);
            if (gr < n) v = *reinterpret_cast<const float4*>(&A[(size_t)gr * K + k0 + c4]);
            As[c4 + 0][row] = v.x;
            As[c4 + 1][row] = v.y;
            As[c4 + 2][row] = v.z;
            As[c4 + 3][row] = v.w;
        }
        // W tile: 16x64, duplicated into (w,w) pairs
        {
            int row = tid >> 4;
            int c4 = (tid & 15) * 4;
            float4 v = *reinterpret_cast<const float4*>(&W[(size_t)(k0 + row) * BN + c4]);
            Ws2[row][c4 + 0] = make_float2(v.x, v.x);
            Ws2[row][c4 + 1] = make_float2(v.y, v.y);
            Ws2[row][c4 + 2] = make_float2(v.z, v.z);
            Ws2[row][c4 + 3] = make_float2(v.w, v.w);
        }
        __syncthreads();
        #pragma unroll
        for (int kk = 0; kk < BK; ++kk) {
            ulonglong2 aA = *reinterpret_cast<const ulonglong2*>(&As[kk][ty * 8]);
            ulonglong2 aB = *reinterpret_cast<const ulonglong2*>(&As[kk][ty * 8 + 4]);
            ulonglong2 w01 = *reinterpret_cast<const ulonglong2*>(&Ws2[kk][tx * 4]);
            ulonglong2 w23 = *reinterpret_cast<const ulonglong2*>(&Ws2[kk][tx * 4 + 2]);
            unsigned long long a[4] = {aA.x, aA.y, aB.x, aB.y};
            unsigned long long w[4] = {w01.x, w01.y, w23.x, w23.y};
            #pragma unroll
            for (int i = 0; i < 4; ++i)
                #pragma unroll
                for (int j = 0; j < 4; ++j)
                    ffma2(acc[i][j], a[i], w[j]);
        }
        __syncthreads();
    }
    #pragma unroll
    for (int i2 = 0; i2 < 4; ++i2) {
        float2 c0 = unpack2(acc[i2][0]);
        float2 c1 = unpack2(acc[i2][1]);
        float2 c2 = unpack2(acc[i2][2]);
        float2 c3 = unpack2(acc[i2][3]);
        int r0 = m0 + ty * 8 + 2 * i2;
        if (r0 < n) {
            float d0 = g_dinv[r0];
            *reinterpret_cast<float4*>(&Cc[(size_t)r0 * 64 + tx * 4]) =
                make_float4(c0.x * d0, c1.x * d0, c2.x * d0, c3.x * d0);
        }
        int r1 = r0 + 1;
        if (r1 < n) {
            float d1 = g_dinv[r1];
            *reinterpret_cast<float4*>(&Cc[(size_t)r1 * 64 + tx * 4]) =
                make_float4(c0.y * d1, c1.y * d1, c2.y * d1, c3.y * d1);
        }
    }
}

// ---------------- aggregation + bias + ELU: one warp per node ----------------
// h is already scaled by dinv[src] (GEMM epilogue); apply dinv[dst] at the end.
__global__ void __launch_bounds__(256) k_agg(const float* __restrict__ h,
                                             const float* __restrict__ bias,
                                             float* __restrict__ out, int n) {
    int node = (blockIdx.x * blockDim.x + threadIdx.x) >> 5;
    int lane = threadIdx.x & 31;
    if (node >= n) return;
    int start = g_rowptr[node];
    int end   = g_rowptr[node + 1];
    float acc0 = 0.f, acc1 = 0.f;
    int j = start;
    for (; j + 4 <= end; j += 4) {
        int s0 = g_csr_src[j];
        int s1 = g_csr_src[j + 1];
        int s2 = g_csr_src[j + 2];
        int s3 = g_csr_src[j + 3];
        const float* p0 = h + (size_t)s0 * 64;
        const float* p1 = h + (size_t)s1 * 64;
        const float* p2 = h + (size_t)s2 * 64;
        const float* p3 = h + (size_t)s3 * 64;
        acc0 += p0[lane];      acc1 += p0[lane + 32];
        acc0 += p1[lane];      acc1 += p1[lane + 32];
        acc0 += p2[lane];      acc1 += p2[lane + 32];
        acc0 += p3[lane];      acc1 += p3[lane + 32];
    }
    for (; j < end; ++j) {
        const float* p = h + (size_t)g_csr_src[j] * 64;
        acc0 += p[lane];
        acc1 += p[lane + 32];
    }
    float dd = g_dinv[node];
    acc0 = acc0 * dd + bias[lane];
    acc1 = acc1 * dd + bias[lane + 32];
    acc0 = acc0 > 0.f ? acc0 : expm1f(acc0);
    acc1 = acc1 > 0.f ? acc1 : expm1f(acc1);
    out[(size_t)node * 64 + lane]      = acc0;
    out[(size_t)node * 64 + lane + 32] = acc1;
}

// ---------------- final classifier: out[n,4] = [Xa|Xb] @ Wfc + bfc ----------------
__global__ void __launch_bounds__(256) k_final(const float* __restrict__ Wfc,
                                               const float* __restrict__ bfc,
                                               float* __restrict__ out, int n) {
    __shared__ float ws[128 * 4];
    for (int i = threadIdx.x; i < 512; i += 256) ws[i] = Wfc[i];
    __syncthreads();
    int node = (blockIdx.x * blockDim.x + threadIdx.x) >> 5;
    int lane = threadIdx.x & 31;
    if (node >= n) return;
    float v0 = g_Xa[(size_t)node * 64 + lane];
    float v1 = g_Xa[(size_t)node * 64 + lane + 32];
    float v2 = g_Xb[(size_t)node * 64 + lane];
    float v3 = g_Xb[(size_t)node * 64 + lane + 32];
    #pragma unroll
    for (int c = 0; c < 4; ++c) {
        float p = v0 * ws[lane * 4 + c]
                + v1 * ws[(lane + 32) * 4 + c]
                + v2 * ws[(64 + lane) * 4 + c]
                + v3 * ws[(96 + lane) * 4 + c];
        #pragma unroll
        for (int off = 16; off; off >>= 1)
            p += __shfl_xor_sync(0xffffffff, p, off);
        if (lane == 0) out[(size_t)node * 4 + c] = p + bfc[c];
    }
}

// ---------------- host launch ----------------
extern "C" void kernel_launch(void* const* d_in, const int* in_sizes, int n_in,
                              void* d_out, int out_size) {
    const float* x1  = (const float*)d_in[0];
    const float* x2  = (const float*)d_in[1];
    const int*   ei  = (const int*)d_in[2];
    const float* W1a = (const float*)d_in[3];
    const float* b1a = (const float*)d_in[4];
    const float* W2a = (const float*)d_in[5];
    const float* b2a = (const float*)d_in[6];
    const float* W1b = (const float*)d_in[7];
    const float* b1b = (const float*)d_in[8];
    const float* W2b = (const float*)d_in[9];
    const float* b2b = (const float*)d_in[10];
    const float* Wfc = (const float*)d_in[11];
    const float* bfc = (const float*)d_in[12];
    float* out = (float*)d_out;

    int n = in_sizes[0] / 512;   // 100000
    int e = in_sizes[2] / 2;     // 1600000
    const int* srcA = ei;
    const int* dstA = ei + e;

    float *pH, *pXa, *pXb;
    cudaGetSymbolAddress((void**)&pH,  g_H);
    cudaGetSymbolAddress((void**)&pXa, g_Xa);
    cudaGetSymbolAddress((void**)&pXb, g_Xb);

    int nblk = (n + 255) / 256;

    // graph build
    k_init_cnt<<<(n + 255) / 256, 256>>>(n);
    k_count<<<(e + 255) / 256, 256>>>(dstA, e);
    k_blocksum<<<nblk, 256>>>(n);
    k_topscan<<<1, 512>>>(nblk);
    k_scanwrite<<<nblk, 256>>>(n);
    k_scatter<<<(e + 255) / 256, 256>>>(srcA, dstA, e);

    int gemm_grid = (n + 127) / 128;
    int node_grid = (n * 32 + 255) / 256;   // one warp per node

    // branch 1
    k_gemm<512><<<gemm_grid, 256>>>(x1, W1a, pH, n);
    k_agg<<<node_grid, 256>>>(pH, b1a, pXa, n);
    k_gemm<64><<<gemm_grid, 256>>>(pXa, W2a, pH, n);
    k_agg<<<node_grid, 256>>>(pH, b2a, pXa, n);

    // branch 2
    k_gemm<256><<<gemm_grid, 256>>>(x2, W1b, pH, n);
    k_agg<<<node_grid, 256>>>(pH, b1b, pXb, n);
    k_gemm<64><<<gemm_grid, 256>>>(pXb, W2b, pH, n);
    k_agg<<<node_grid, 256>>>(pH, b2b, pXb, n);

    // classifier
    k_final<<<node_grid, 256>>>(Wfc, bfc, out, n);
}

// round 9
// speedup vs baseline: 1.3613x; 1.3613x over previous
#include <cuda_runtime.h>
#include <cstdint>

// Problem constants (fixed by the dataset)
#define NMAX 100000
#define EMAX 1600000
#define HID  64

// ---------------- device scratch (no allocations allowed) ----------------
__device__ int   g_cnt[NMAX];
__device__ float g_dinv[NMAX];
__device__ int   g_rowptr[NMAX + 1];
__device__ int   g_woff[NMAX];
__device__ int   g_bsum[512];
__device__ int   g_boff[512];
__device__ int   g_csr_src[EMAX + NMAX];
__device__ float g_H [(size_t)NMAX * HID];
__device__ float g_Xa[(size_t)NMAX * HID];
__device__ float g_Xb[(size_t)NMAX * HID];

// ---------------- tf32 helpers ----------------
__device__ __forceinline__ float tf32r(float x) {
    unsigned u;
    asm("cvt.rna.tf32.f32 %0, %1;" : "=r"(u) : "f"(x));
    return __uint_as_float(u);
}

__device__ __forceinline__ void mma_tf32(float* d, const unsigned* a, const unsigned* b) {
    asm("mma.sync.aligned.m16n8k8.row.col.f32.tf32.tf32.f32 "
        "{%0,%1,%2,%3}, {%4,%5,%6,%7}, {%8,%9}, {%0,%1,%2,%3};"
        : "+f"(d[0]), "+f"(d[1]), "+f"(d[2]), "+f"(d[3])
        : "r"(a[0]), "r"(a[1]), "r"(a[2]), "r"(a[3]),
          "r"(b[0]), "r"(b[1]));
}

// ---------------- graph build ----------------
__global__ void k_init_cnt(int n) {
    int i = blockIdx.x * blockDim.x + threadIdx.x;
    if (i < n) g_cnt[i] = 1;   // self-loop
}

__global__ void k_count(const int* __restrict__ dst, int e) {
    int i = blockIdx.x * blockDim.x + threadIdx.x;
    if (i < e) atomicAdd(&g_cnt[dst[i]], 1);
}

__global__ void k_blocksum(int n) {
    __shared__ int sh[256];
    int i = blockIdx.x * 256 + threadIdx.x;
    sh[threadIdx.x] = (i < n) ? g_cnt[i] : 0;
    __syncthreads();
    for (int off = 128; off; off >>= 1) {
        if (threadIdx.x < off) sh[threadIdx.x] += sh[threadIdx.x + off];
        __syncthreads();
    }
    if (threadIdx.x == 0) g_bsum[blockIdx.x] = sh[0];
}

// single block, 512 threads: exclusive scan of block sums
__global__ void k_topscan(int nblk) {
    __shared__ int sh[512];
    int t = threadIdx.x;
    int v = (t < nblk) ? g_bsum[t] : 0;
    sh[t] = v;
    for (int off = 1; off < 512; off <<= 1) {
        __syncthreads();
        int x = (t >= off) ? sh[t - off] : 0;
        __syncthreads();
        sh[t] += x;
    }
    __syncthreads();
    if (t < nblk) g_boff[t] = sh[t] - v;   // exclusive
}

__global__ void k_scanwrite(int n) {
    __shared__ int sh[256];
    int t = threadIdx.x;
    int i = blockIdx.x * 256 + t;
    int v = (i < n) ? g_cnt[i] : 0;
    sh[t] = v;
    for (int off = 1; off < 256; off <<= 1) {
        __syncthreads();
        int x = (t >= off) ? sh[t - off] : 0;
        __syncthreads();
        sh[t] += x;
    }
    __syncthreads();
    int excl = sh[t] - v;
    if (i < n) {
        int rp = g_boff[blockIdx.x] + excl;
        g_rowptr[i] = rp;
        g_dinv[i] = rsqrtf((float)v);
        // self-loop edge first (deterministic slot)
        g_csr_src[rp] = i;
        g_woff[i] = rp + 1;
        if (i == n - 1) g_rowptr[n] = rp + v;
    }
}

__global__ void k_scatter(const int* __restrict__ src, const int* __restrict__ dst, int e) {
    int i = blockIdx.x * blockDim.x + threadIdx.x;
    if (i >= e) return;
    int d = dst[i];
    int pos = atomicAdd(&g_woff[d], 1);
    g_csr_src[pos] = src[i];
}

// ---------------- tensor-core GEMM: C[r,:] = dinv[r] * (A[r,:K] @ W[K,64]) ----
// 3xTF32 split for fp32 accuracy: x = hi + lo (both tf32-rounded),
// D = Ahi*Bhi + Ahi*Blo + Alo*Bhi  (lo*lo term ~2^-22, dropped).
// Block: 128 rows x 64 cols, 8 warps; warp w owns rows w*16..w*16+15 and all
// 8 n-tiles of m16n8k8. Padded smem (PA=136, PW=72) makes every fragment LDS
// bank-conflict-free ((8q+g) mod 32 is a permutation).
template <int K>
__global__ void __launch_bounds__(256) k_gemm_tc(const float* __restrict__ A,
                                                 const float* __restrict__ W,
                                                 float* __restrict__ Cc, int n) {
    constexpr int BM = 128, BK = 16, PA = 136, PW = 72;
    __shared__ float As_hi[BK][PA];
    __shared__ float As_lo[BK][PA];
    __shared__ float Ws_hi[BK][PW];
    __shared__ float Ws_lo[BK][PW];
    int tid  = threadIdx.x;
    int warp = tid >> 5;
    int lane = tid & 31;
    int q = lane & 3;        // threadID_in_group
    int g = lane >> 2;       // groupID
    int m0 = blockIdx.x * BM;
    int mw = warp * 16;
    float acc[8][4];
    #pragma unroll
    for (int t = 0; t < 8; ++t)
        #pragma unroll
        for (int j = 0; j < 4; ++j) acc[t][j] = 0.f;

    for (int k0 = 0; k0 < K; k0 += BK) {
        // A tile: 128x16 floats = 512 float4 loads, 2 per thread, stored [k][m]
        #pragma unroll
        for (int r = 0; r < 2; ++r) {
            int idx = tid + r * 256;      // 0..511
            int row = idx >> 2;           // 0..127
            int c4  = (idx & 3) * 4;      // 0,4,8,12
            int gr  = m0 + row;
            float4 v = make_float4(0.f, 0.f, 0.f, 0.f);
            if (gr < n) v = *reinterpret_cast<const float4*>(&A[(size_t)gr * K + k0 + c4]);
            float xs[4] = {v.x, v.y, v.z, v.w};
            #pragma unroll
            for (int i = 0; i < 4; ++i) {
                float hi = tf32r(xs[i]);
                As_hi[c4 + i][row] = hi;
                As_lo[c4 + i][row] = tf32r(xs[i] - hi);
            }
        }
        // W tile: 16x64 floats = 256 float4 loads, 1 per thread
        {
            int row = tid >> 4;           // k 0..15
            int c4  = (tid & 15) * 4;     // n 0..60
            float4 v = *reinterpret_cast<const float4*>(&W[(size_t)(k0 + row) * 64 + c4]);
            float xs[4] = {v.x, v.y, v.z, v.w};
            #pragma unroll
            for (int i = 0; i < 4; ++i) {
                float hi = tf32r(xs[i]);
                Ws_hi[row][c4 + i] = hi;
                Ws_lo[row][c4 + i] = tf32r(xs[i] - hi);
            }
        }
        __syncthreads();
        #pragma unroll
        for (int kk = 0; kk < 2; ++kk) {
            int kb = kk * 8;
            unsigned ah[4], al[4];
            ah[0] = __float_as_uint(As_hi[kb + q    ][mw + g    ]);
            ah[1] = __float_as_uint(As_hi[kb + q    ][mw + g + 8]);
            ah[2] = __float_as_uint(As_hi[kb + q + 4][mw + g    ]);
            ah[3] = __float_as_uint(As_hi[kb + q + 4][mw + g + 8]);
            al[0] = __float_as_uint(As_lo[kb + q    ][mw + g    ]);
            al[1] = __float_as_uint(As_lo[kb + q    ][mw + g + 8]);
            al[2] = __float_as_uint(As_lo[kb + q + 4][mw + g    ]);
            al[3] = __float_as_uint(As_lo[kb + q + 4][mw + g + 8]);
            #pragma unroll
            for (int nt = 0; nt < 8; ++nt) {
                unsigned bh[2], bl[2];
                bh[0] = __float_as_uint(Ws_hi[kb + q    ][nt * 8 + g]);
                bh[1] = __float_as_uint(Ws_hi[kb + q + 4][nt * 8 + g]);
                bl[0] = __float_as_uint(Ws_lo[kb + q    ][nt * 8 + g]);
                bl[1] = __float_as_uint(Ws_lo[kb + q + 4][nt * 8 + g]);
                mma_tf32(acc[nt], ah, bh);
                mma_tf32(acc[nt], ah, bl);
                mma_tf32(acc[nt], al, bh);
            }
        }
        __syncthreads();
    }
    // epilogue: scale rows by dinv, write float2 per C-fragment half
    int r0 = m0 + mw + g;
    int r1 = r0 + 8;
    float d0 = (r0 < n) ? g_dinv[r0] : 0.f;
    float d1 = (r1 < n) ? g_dinv[r1] : 0.f;
    #pragma unroll
    for (int nt = 0; nt < 8; ++nt) {
        int col = nt * 8 + q * 2;
        if (r0 < n)
            *reinterpret_cast<float2*>(&Cc[(size_t)r0 * 64 + col]) =
                make_float2(acc[nt][0] * d0, acc[nt][1] * d0);
        if (r1 < n)
            *reinterpret_cast<float2*>(&Cc[(size_t)r1 * 64 + col]) =
                make_float2(acc[nt][2] * d1, acc[nt][3] * d1);
    }
}

// ---------------- aggregation + bias + ELU: one warp per node ----------------
// h is already scaled by dinv[src] (GEMM epilogue); apply dinv[dst] at the end.
__global__ void __launch_bounds__(256) k_agg(const float* __restrict__ h,
                                             const float* __restrict__ bias,
                                             float* __restrict__ out, int n) {
    int node = (blockIdx.x * blockDim.x + threadIdx.x) >> 5;
    int lane = threadIdx.x & 31;
    if (node >= n) return;
    int start = g_rowptr[node];
    int end   = g_rowptr[node + 1];
    float acc0 = 0.f, acc1 = 0.f;
    int j = start;
    for (; j + 4 <= end; j += 4) {
        int s0 = g_csr_src[j];
        int s1 = g_csr_src[j + 1];
        int s2 = g_csr_src[j + 2];
        int s3 = g_csr_src[j + 3];
        const float* p0 = h + (size_t)s0 * 64;
        const float* p1 = h + (size_t)s1 * 64;
        const float* p2 = h + (size_t)s2 * 64;
        const float* p3 = h + (size_t)s3 * 64;
        acc0 += p0[lane];      acc1 += p0[lane + 32];
        acc0 += p1[lane];      acc1 += p1[lane + 32];
        acc0 += p2[lane];      acc1 += p2[lane + 32];
        acc0 += p3[lane];      acc1 += p3[lane + 32];
    }
    for (; j < end; ++j) {
        const float* p = h + (size_t)g_csr_src[j] * 64;
        acc0 += p[lane];
        acc1 += p[lane + 32];
    }
    float dd = g_dinv[node];
    acc0 = acc0 * dd + bias[lane];
    acc1 = acc1 * dd + bias[lane + 32];
    acc0 = acc0 > 0.f ? acc0 : expm1f(acc0);
    acc1 = acc1 > 0.f ? acc1 : expm1f(acc1);
    out[(size_t)node * 64 + lane]      = acc0;
    out[(size_t)node * 64 + lane + 32] = acc1;
}

// ---------------- final classifier: out[n,4] = [Xa|Xb] @ Wfc + bfc ----------------
__global__ void __launch_bounds__(256) k_final(const float* __restrict__ Wfc,
                                               const float* __restrict__ bfc,
                                               float* __restrict__ out, int n) {
    __shared__ float ws[128 * 4];
    for (int i = threadIdx.x; i < 512; i += 256) ws[i] = Wfc[i];
    __syncthreads();
    int node = (blockIdx.x * blockDim.x + threadIdx.x) >> 5;
    int lane = threadIdx.x & 31;
    if (node >= n) return;
    float v0 = g_Xa[(size_t)node * 64 + lane];
    float v1 = g_Xa[(size_t)node * 64 + lane + 32];
    float v2 = g_Xb[(size_t)node * 64 + lane];
    float v3 = g_Xb[(size_t)node * 64 + lane + 32];
    #pragma unroll
    for (int c = 0; c < 4; ++c) {
        float p = v0 * ws[lane * 4 + c]
                + v1 * ws[(lane + 32) * 4 + c]
                + v2 * ws[(64 + lane) * 4 + c]
                + v3 * ws[(96 + lane) * 4 + c];
        #pragma unroll
        for (int off = 16; off; off >>= 1)
            p += __shfl_xor_sync(0xffffffff, p, off);
        if (lane == 0) out[(size_t)node * 4 + c] = p + bfc[c];
    }
}

// ---------------- host launch ----------------
extern "C" void kernel_launch(void* const* d_in, const int* in_sizes, int n_in,
                              void* d_out, int out_size) {
    const float* x1  = (const float*)d_in[0];
    const float* x2  = (const float*)d_in[1];
    const int*   ei  = (const int*)d_in[2];
    const float* W1a = (const float*)d_in[3];
    const float* b1a = (const float*)d_in[4];
    const float* W2a = (const float*)d_in[5];
    const float* b2a = (const float*)d_in[6];
    const float* W1b = (const float*)d_in[7];
    const float* b1b = (const float*)d_in[8];
    const float* W2b = (const float*)d_in[9];
    const float* b2b = (const float*)d_in[10];
    const float* Wfc = (const float*)d_in[11];
    const float* bfc = (const float*)d_in[12];
    float* out = (float*)d_out;

    int n = in_sizes[0] / 512;   // 100000
    int e = in_sizes[2] / 2;     // 1600000
    const int* srcA = ei;
    const int* dstA = ei + e;

    float *pH, *pXa, *pXb;
    cudaGetSymbolAddress((void**)&pH,  g_H);
    cudaGetSymbolAddress((void**)&pXa, g_Xa);
    cudaGetSymbolAddress((void**)&pXb, g_Xb);

    int nblk = (n + 255) / 256;

    // graph build
    k_init_cnt<<<(n + 255) / 256, 256>>>(n);
    k_count<<<(e + 255) / 256, 256>>>(dstA, e);
    k_blocksum<<<nblk, 256>>>(n);
    k_topscan<<<1, 512>>>(nblk);
    k_scanwrite<<<nblk, 256>>>(n);
    k_scatter<<<(e + 255) / 256, 256>>>(srcA, dstA, e);

    int gemm_grid = (n + 127) / 128;
    int node_grid = (n * 32 + 255) / 256;   // one warp per node

    // branch 1
    k_gemm_tc<512><<<gemm_grid, 256>>>(x1, W1a, pH, n);
    k_agg<<<node_grid, 256>>>(pH, b1a, pXa, n);
    k_gemm_tc<64><<<gemm_grid, 256>>>(pXa, W2a, pH, n);
    k_agg<<<node_grid, 256>>>(pH, b2a, pXa, n);

    // branch 2
    k_gemm_tc<256><<<gemm_grid, 256>>>(x2, W1b, pH, n);
    k_agg<<<node_grid, 256>>>(pH, b1b, pXb, n);
    k_gemm_tc<64><<<gemm_grid, 256>>>(pXb, W2b, pH, n);
    k_agg<<<node_grid, 256>>>(pH, b2b, pXb, n);

    // classifier
    k_final<<<node_grid, 256>>>(Wfc, bfc, out, n);
}

// round 11
// speedup vs baseline: 2.0243x; 1.4871x over previous
#include <cuda_runtime.h>
#include <cstdint>

// Problem constants (fixed by the dataset)
#define NMAX 100000
#define EMAX 1600000
#define HID  64

// ---------------- device scratch (no allocations allowed) ----------------
__device__ int   g_cnt[NMAX];
__device__ float g_dinv[NMAX];
__device__ int   g_rowptr[NMAX + 1];
__device__ int   g_woff[NMAX];
__device__ int   g_bsum[512];
__device__ int   g_boff[512];
__device__ int   g_csr_src[EMAX + NMAX];
__device__ float g_Ha[(size_t)NMAX * HID];
__device__ float g_Hb[(size_t)NMAX * HID];
__device__ float g_Xa[(size_t)NMAX * HID];
__device__ float g_Xb[(size_t)NMAX * HID];

// ---------------- bf16 split helpers ----------------
// hi = top-16-bit truncation of fp32 (exact bf16, RZ); lo = RN bf16 of residual.
__device__ __forceinline__ unsigned prmt_hipack(unsigned a, unsigned b) {
    // result = { lo16 = a[31:16], hi16 = b[31:16] }
    unsigned r;
    asm("prmt.b32 %0, %1, %2, 0x7632;" : "=r"(r) : "r"(a), "r"(b));
    return r;
}
__device__ __forceinline__ unsigned bf16x2_rn(float lo_elem, float hi_elem) {
    // low half <- lo_elem, high half <- hi_elem (first asm source fills high)
    unsigned r;
    asm("cvt.rn.bf16x2.f32 %0, %1, %2;" : "=r"(r) : "f"(hi_elem), "f"(lo_elem));
    return r;
}
__device__ __forceinline__ float trunc_bf16f(float x) {
    return __uint_as_float(__float_as_uint(x) & 0xFFFF0000u);
}

__device__ __forceinline__ void mma_bf16(float* d, const unsigned* a, const unsigned* b) {
    asm("mma.sync.aligned.m16n8k16.row.col.f32.bf16.bf16.f32 "
        "{%0,%1,%2,%3}, {%4,%5,%6,%7}, {%8,%9}, {%0,%1,%2,%3};"
        : "+f"(d[0]), "+f"(d[1]), "+f"(d[2]), "+f"(d[3])
        : "r"(a[0]), "r"(a[1]), "r"(a[2]), "r"(a[3]),
          "r"(b[0]), "r"(b[1]));
}

// ---------------- graph build ----------------
__global__ void k_init_cnt(int n) {
    int i = blockIdx.x * blockDim.x + threadIdx.x;
    if (i < n) g_cnt[i] = 1;   // self-loop
}

__global__ void k_count(const int* __restrict__ dst, int e) {
    int i = blockIdx.x * blockDim.x + threadIdx.x;
    if (i < e) atomicAdd(&g_cnt[dst[i]], 1);
}

__global__ void k_blocksum(int n) {
    __shared__ int sh[256];
    int i = blockIdx.x * 256 + threadIdx.x;
    sh[threadIdx.x] = (i < n) ? g_cnt[i] : 0;
    __syncthreads();
    for (int off = 128; off; off >>= 1) {
        if (threadIdx.x < off) sh[threadIdx.x] += sh[threadIdx.x + off];
        __syncthreads();
    }
    if (threadIdx.x == 0) g_bsum[blockIdx.x] = sh[0];
}

// single block, 512 threads: exclusive scan of block sums
__global__ void k_topscan(int nblk) {
    __shared__ int sh[512];
    int t = threadIdx.x;
    int v = (t < nblk) ? g_bsum[t] : 0;
    sh[t] = v;
    for (int off = 1; off < 512; off <<= 1) {
        __syncthreads();
        int x = (t >= off) ? sh[t - off] : 0;
        __syncthreads();
        sh[t] += x;
    }
    __syncthreads();
    if (t < nblk) g_boff[t] = sh[t] - v;   // exclusive
}

__global__ void k_scanwrite(int n) {
    __shared__ int sh[256];
    int t = threadIdx.x;
    int i = blockIdx.x * 256 + t;
    int v = (i < n) ? g_cnt[i] : 0;
    sh[t] = v;
    for (int off = 1; off < 256; off <<= 1) {
        __syncthreads();
        int x = (t >= off) ? sh[t - off] : 0;
        __syncthreads();
        sh[t] += x;
    }
    __syncthreads();
    int excl = sh[t] - v;
    if (i < n) {
        int rp = g_boff[blockIdx.x] + excl;
        g_rowptr[i] = rp;
        g_dinv[i] = rsqrtf((float)v);
        // self-loop edge first (deterministic slot)
        g_csr_src[rp] = i;
        g_woff[i] = rp + 1;
        if (i == n - 1) g_rowptr[n] = rp + v;
    }
}

__global__ void k_scatter(const int* __restrict__ src, const int* __restrict__ dst, int e) {
    int i = blockIdx.x * blockDim.x + threadIdx.x;
    if (i >= e) return;
    int d = dst[i];
    int pos = atomicAdd(&g_woff[d], 1);
    g_csr_src[pos] = src[i];
}

// ---------------- dual tensor-core GEMM ---------------------------------
// Two independent problems in one launch (blockIdx < nb0 -> problem 0).
// C[r,:] = dinv[r] * (A[r,:K] @ W[K,64]), bf16 hi/lo 3-split on
// mma.m16n8k16 (hi*hi + hi*lo + lo*hi), fp32 accumulate.
// Block 128x64, 8 warps as 4 row-groups x 2 col-groups; warp = 32 rows x 32 cols
// = 2 m-tiles x 4 n-tiles. Smem word-stride 12 -> conflict-free fragment LDS.
__global__ void __launch_bounds__(256) k_gemm_dual(
        const float* __restrict__ A0, const float* __restrict__ W0, int K0,
        float* __restrict__ C0, int nb0,
        const float* __restrict__ A1, const float* __restrict__ W1, int K1,
        float* __restrict__ C1, int n) {
    constexpr int BM = 128, BK = 16, AST = 12, WST = 12;  // strides in 32-bit words
    __shared__ unsigned Ah[BM][AST];
    __shared__ unsigned Al[BM][AST];
    __shared__ unsigned Wh[64][WST];
    __shared__ unsigned Wl[64][WST];

    const float* A; const float* W; float* Cc; int K; int m0;
    if (blockIdx.x < nb0) { A = A0; W = W0; Cc = C0; K = K0; m0 = blockIdx.x * BM; }
    else                  { A = A1; W = W1; Cc = C1; K = K1; m0 = (blockIdx.x - nb0) * BM; }

    int tid  = threadIdx.x;
    int warp = tid >> 5;
    int lane = tid & 31;
    int q = lane & 3;        // threadID_in_group
    int g = lane >> 2;       // groupID
    int rg = warp & 3;       // row-group: rows rg*32 .. rg*32+31
    int cg = warp >> 2;      // col-group: cols cg*32 .. cg*32+31
    int mrow = rg * 32;
    int ncol = cg * 32;

    float acc[2][4][4];
    #pragma unroll
    for (int mt = 0; mt < 2; ++mt)
        #pragma unroll
        for (int nt = 0; nt < 4; ++nt)
            #pragma unroll
            for (int j = 0; j < 4; ++j) acc[mt][nt][j] = 0.f;

    // staging coords
    int a_row = tid >> 2;                // 0..63 (+64 on second pass)
    int a_c4  = (tid & 3) * 4;           // k offset 0,4,8,12
    int w_col = tid & 63;                // 0..63
    int w_kb  = (tid >> 6) * 4;          // 0,4,8,12

    for (int k0 = 0; k0 < K; k0 += BK) {
        // --- stage A tile: 128x16, hi via PRMT truncation, lo via RN bf16 ---
        #pragma unroll
        for (int r = 0; r < 2; ++r) {
            int row = a_row + r * 64;
            int gr  = m0 + row;
            float4 v = make_float4(0.f, 0.f, 0.f, 0.f);
            if (gr < n) v = *reinterpret_cast<const float4*>(&A[(size_t)gr * K + k0 + a_c4]);
            unsigned bx = __float_as_uint(v.x), by = __float_as_uint(v.y);
            unsigned bz = __float_as_uint(v.z), bw = __float_as_uint(v.w);
            Ah[row][(a_c4 >> 1)    ] = prmt_hipack(bx, by);
            Ah[row][(a_c4 >> 1) + 1] = prmt_hipack(bz, bw);
            Al[row][(a_c4 >> 1)    ] = bf16x2_rn(v.x - trunc_bf16f(v.x), v.y - trunc_bf16f(v.y));
            Al[row][(a_c4 >> 1) + 1] = bf16x2_rn(v.z - trunc_bf16f(v.z), v.w - trunc_bf16f(v.w));
        }
        // --- stage W tile: 16x64, each thread 4 consecutive k for one col ---
        {
            float w0 = W[(size_t)(k0 + w_kb + 0) * 64 + w_col];
            float w1 = W[(size_t)(k0 + w_kb + 1) * 64 + w_col];
            float w2 = W[(size_t)(k0 + w_kb + 2) * 64 + w_col];
            float w3 = W[(size_t)(k0 + w_kb + 3) * 64 + w_col];
            Wh[w_col][(w_kb >> 1)    ] = prmt_hipack(__float_as_uint(w0), __float_as_uint(w1));
            Wh[w_col][(w_kb >> 1) + 1] = prmt_hipack(__float_as_uint(w2), __float_as_uint(w3));
            Wl[w_col][(w_kb >> 1)    ] = bf16x2_rn(w0 - trunc_bf16f(w0), w1 - trunc_bf16f(w1));
            Wl[w_col][(w_kb >> 1) + 1] = bf16x2_rn(w2 - trunc_bf16f(w2), w3 - trunc_bf16f(w3));
        }
        __syncthreads();

        // --- fragment loads + MMAs (one 16-k step) ---
        unsigned ah[2][4], al[2][4];
        #pragma unroll
        for (int mt = 0; mt < 2; ++mt) {
            int rbase = mrow + mt * 16;
            ah[mt][0] = Ah[rbase + g    ][q    ];
            ah[mt][1] = Ah[rbase + g + 8][q    ];
            ah[mt][2] = Ah[rbase + g    ][q + 4];
            ah[mt][3] = Ah[rbase + g + 8][q + 4];
            al[mt][0] = Al[rbase + g    ][q    ];
            al[mt][1] = Al[rbase + g + 8][q    ];
            al[mt][2] = Al[rbase + g    ][q + 4];
            al[mt][3] = Al[rbase + g + 8][q + 4];
        }
        #pragma unroll
        for (int nt = 0; nt < 4; ++nt) {
            int col = ncol + nt * 8 + g;
            unsigned bh[2], bl[2];
            bh[0] = Wh[col][q];
            bh[1] = Wh[col][q + 4];
            bl[0] = Wl[col][q];
            bl[1] = Wl[col][q + 4];
            #pragma unroll
            for (int mt = 0; mt < 2; ++mt) {
                mma_bf16(acc[mt][nt], ah[mt], bh);
                mma_bf16(acc[mt][nt], ah[mt], bl);
                mma_bf16(acc[mt][nt], al[mt], bh);
            }
        }
        __syncthreads();
    }

    // epilogue: scale rows by dinv, write float2 fragments
    #pragma unroll
    for (int mt = 0; mt < 2; ++mt) {
        int r0 = m0 + mrow + mt * 16 + g;
        int r1 = r0 + 8;
        float d0 = (r0 < n) ? g_dinv[r0] : 0.f;
        float d1 = (r1 < n) ? g_dinv[r1] : 0.f;
        #pragma unroll
        for (int nt = 0; nt < 4; ++nt) {
            int col = ncol + nt * 8 + q * 2;
            if (r0 < n)
                *reinterpret_cast<float2*>(&Cc[(size_t)r0 * 64 + col]) =
                    make_float2(acc[mt][nt][0] * d0, acc[mt][nt][1] * d0);
            if (r1 < n)
                *reinterpret_cast<float2*>(&Cc[(size_t)r1 * 64 + col]) =
                    make_float2(acc[mt][nt][2] * d1, acc[mt][nt][3] * d1);
        }
    }
}

// ---------------- dual aggregation + bias + ELU: one warp per node ----------
// h is pre-scaled by dinv[src] (GEMM epilogue); apply dinv[dst] at the end.
// Lane covers cols 2*lane, 2*lane+1 -> one LDG.64 per edge.
__global__ void __launch_bounds__(256) k_agg_dual(
        const float* __restrict__ h0, const float* __restrict__ b0, float* __restrict__ o0,
        const float* __restrict__ h1, const float* __restrict__ b1, float* __restrict__ o1,
        int n) {
    int w = (blockIdx.x * blockDim.x + threadIdx.x) >> 5;
    int lane = threadIdx.x & 31;
    const float* h; const float* bias; float* o; int node;
    if (w < n)          { node = w;     h = h0; bias = b0; o = o0; }
    else if (w < 2 * n) { node = w - n; h = h1; bias = b1; o = o1; }
    else return;

    const float2* hp = reinterpret_cast<const float2*>(h);
    int start = g_rowptr[node];
    int end   = g_rowptr[node + 1];
    float ax = 0.f, ay = 0.f;
    int j = start;
    for (; j + 4 <= end; j += 4) {
        int s0 = g_csr_src[j];
        int s1 = g_csr_src[j + 1];
        int s2 = g_csr_src[j + 2];
        int s3 = g_csr_src[j + 3];
        float2 v0 = hp[(size_t)s0 * 32 + lane];
        float2 v1 = hp[(size_t)s1 * 32 + lane];
        float2 v2 = hp[(size_t)s2 * 32 + lane];
        float2 v3 = hp[(size_t)s3 * 32 + lane];
        ax += v0.x + v1.x + v2.x + v3.x;
        ay += v0.y + v1.y + v2.y + v3.y;
    }
    for (; j < end; ++j) {
        float2 v = hp[(size_t)g_csr_src[j] * 32 + lane];
        ax += v.x;
        ay += v.y;
    }
    float dd = g_dinv[node];
    float2 bb = reinterpret_cast<const float2*>(bias)[lane];
    ax = ax * dd + bb.x;
    ay = ay * dd + bb.y;
    ax = ax > 0.f ? ax : expm1f(ax);
    ay = ay > 0.f ? ay : expm1f(ay);
    reinterpret_cast<float2*>(o)[(size_t)node * 32 + lane] = make_float2(ax, ay);
}

// ---------------- final classifier: out[n,4] = [Xa|Xb] @ Wfc + bfc ----------------
__global__ void __launch_bounds__(256) k_final(const float* __restrict__ Wfc,
                                               const float* __restrict__ bfc,
                                               float* __restrict__ out, int n) {
    __shared__ float ws[128 * 4];
    for (int i = threadIdx.x; i < 512; i += 256) ws[i] = Wfc[i];
    __syncthreads();
    int node = (blockIdx.x * blockDim.x + threadIdx.x) >> 5;
    int lane = threadIdx.x & 31;
    if (node >= n) return;
    float v0 = g_Xa[(size_t)node * 64 + lane];
    float v1 = g_Xa[(size_t)node * 64 + lane + 32];
    float v2 = g_Xb[(size_t)node * 64 + lane];
    float v3 = g_Xb[(size_t)node * 64 + lane + 32];
    #pragma unroll
    for (int c = 0; c < 4; ++c) {
        float p = v0 * ws[lane * 4 + c]
                + v1 * ws[(lane + 32) * 4 + c]
                + v2 * ws[(64 + lane) * 4 + c]
                + v3 * ws[(96 + lane) * 4 + c];
        #pragma unroll
        for (int off = 16; off; off >>= 1)
            p += __shfl_xor_sync(0xffffffff, p, off);
        if (lane == 0) out[(size_t)node * 4 + c] = p + bfc[c];
    }
}

// ---------------- host launch ----------------
extern "C" void kernel_launch(void* const* d_in, const int* in_sizes, int n_in,
                              void* d_out, int out_size) {
    const float* x1  = (const float*)d_in[0];
    const float* x2  = (const float*)d_in[1];
    const int*   ei  = (const int*)d_in[2];
    const float* W1a = (const float*)d_in[3];
    const float* b1a = (const float*)d_in[4];
    const float* W2a = (const float*)d_in[5];
    const float* b2a = (const float*)d_in[6];
    const float* W1b = (const float*)d_in[7];
    const float* b1b = (const float*)d_in[8];
    const float* W2b = (const float*)d_in[9];
    const float* b2b = (const float*)d_in[10];
    const float* Wfc = (const float*)d_in[11];
    const float* bfc = (const float*)d_in[12];
    float* out = (float*)d_out;

    int n = in_sizes[0] / 512;   // 100000
    int e = in_sizes[2] / 2;     // 1600000
    const int* srcA = ei;
    const int* dstA = ei + e;

    float *pHa, *pHb, *pXa, *pXb;
    cudaGetSymbolAddress((void**)&pHa, g_Ha);
    cudaGetSymbolAddress((void**)&pHb, g_Hb);
    cudaGetSymbolAddress((void**)&pXa, g_Xa);
    cudaGetSymbolAddress((void**)&pXb, g_Xb);

    int nblk = (n + 255) / 256;

    // graph build
    k_init_cnt<<<(n + 255) / 256, 256>>>(n);
    k_count<<<(e + 255) / 256, 256>>>(dstA, e);
    k_blocksum<<<nblk, 256>>>(n);
    k_topscan<<<1, 512>>>(nblk);
    k_scanwrite<<<nblk, 256>>>(n);
    k_scatter<<<(e + 255) / 256, 256>>>(srcA, dstA, e);

    int nb = (n + 127) / 128;                       // 782
    int agg_grid = (2 * n * 32 + 255) / 256;        // two branches fused
    int fin_grid = (n * 32 + 255) / 256;

    // layer 1 (both branches fused)
    k_gemm_dual<<<2 * nb, 256>>>(x1, W1a, 512, pHa, nb, x2, W1b, 256, pHb, n);
    k_agg_dual<<<agg_grid, 256>>>(pHa, b1a, pXa, pHb, b1b, pXb, n);

    // layer 2 (both branches fused)
    k_gemm_dual<<<2 * nb, 256>>>(pXa, W2a, 64, pHa, nb, pXb, W2b, 64, pHb, n);
    k_agg_dual<<<agg_grid, 256>>>(pHa, b2a, pXa, pHb, b2b, pXb, n);

    // classifier
    k_final<<<fin_grid, 256>>>(Wfc, bfc, out, n);
}

// round 14
// speedup vs baseline: 2.4506x; 1.2106x over previous
#include <cuda_runtime.h>
#include <cuda_fp16.h>
#include <cstdint>

// Problem constants (fixed by the dataset)
#define NMAX 100000
#define EMAX 1600000
#define HID  64

// ---------------- device scratch (no allocations allowed) ----------------
__device__ int    g_cnt[NMAX];
__device__ float  g_dinv[NMAX];
__device__ int    g_rowptr[NMAX + 1];
__device__ int    g_woff[NMAX];
__device__ int    g_bsum[512];
__device__ int    g_boff[512];
__device__ int    g_csr_src[EMAX + NMAX];
__device__ __half g_Hh[(size_t)NMAX * 128];   // interleaved: cols 0-63 branch a, 64-127 branch b
__device__ float  g_Xa[(size_t)NMAX * HID];
__device__ float  g_Xb[(size_t)NMAX * HID];

// ---------------- bf16 split helpers ----------------
// hi = top-16-bit truncation of fp32 (exact bf16, RZ); lo = RN bf16 of residual.
__device__ __forceinline__ unsigned prmt_hipack(unsigned a, unsigned b) {
    unsigned r;
    asm("prmt.b32 %0, %1, %2, 0x7632;" : "=r"(r) : "r"(a), "r"(b));
    return r;
}
__device__ __forceinline__ unsigned bf16x2_rn(float lo_elem, float hi_elem) {
    unsigned r;
    asm("cvt.rn.bf16x2.f32 %0, %1, %2;" : "=r"(r) : "f"(hi_elem), "f"(lo_elem));
    return r;
}
__device__ __forceinline__ float trunc_bf16f(float x) {
    return __uint_as_float(__float_as_uint(x) & 0xFFFF0000u);
}

__device__ __forceinline__ void mma_bf16(float* d, const unsigned* a, const unsigned* b) {
    asm("mma.sync.aligned.m16n8k16.row.col.f32.bf16.bf16.f32 "
        "{%0,%1,%2,%3}, {%4,%5,%6,%7}, {%8,%9}, {%0,%1,%2,%3};"
        : "+f"(d[0]), "+f"(d[1]), "+f"(d[2]), "+f"(d[3])
        : "r"(a[0]), "r"(a[1]), "r"(a[2]), "r"(a[3]),
          "r"(b[0]), "r"(b[1]));
}

// ---------------- graph build ----------------
__global__ void k_init_cnt(int n) {
    int i = blockIdx.x * blockDim.x + threadIdx.x;
    if (i < n) g_cnt[i] = 1;   // self-loop
}

__global__ void k_count(const int* __restrict__ dst, int e) {
    int i = blockIdx.x * blockDim.x + threadIdx.x;
    if (i < e) atomicAdd(&g_cnt[dst[i]], 1);
}

__global__ void k_blocksum(int n) {
    __shared__ int sh[256];
    int i = blockIdx.x * 256 + threadIdx.x;
    sh[threadIdx.x] = (i < n) ? g_cnt[i] : 0;
    __syncthreads();
    for (int off = 128; off; off >>= 1) {
        if (threadIdx.x < off) sh[threadIdx.x] += sh[threadIdx.x + off];
        __syncthreads();
    }
    if (threadIdx.x == 0) g_bsum[blockIdx.x] = sh[0];
}

// single block, 512 threads: exclusive scan of block sums
__global__ void k_topscan(int nblk) {
    __shared__ int sh[512];
    int t = threadIdx.x;
    int v = (t < nblk) ? g_bsum[t] : 0;
    sh[t] = v;
    for (int off = 1; off < 512; off <<= 1) {
        __syncthreads();
        int x = (t >= off) ? sh[t - off] : 0;
        __syncthreads();
        sh[t] += x;
    }
    __syncthreads();
    if (t < nblk) g_boff[t] = sh[t] - v;   // exclusive
}

__global__ void k_scanwrite(int n) {
    __shared__ int sh[256];
    int t = threadIdx.x;
    int i = blockIdx.x * 256 + t;
    int v = (i < n) ? g_cnt[i] : 0;
    sh[t] = v;
    for (int off = 1; off < 256; off <<= 1) {
        __syncthreads();
        int x = (t >= off) ? sh[t - off] : 0;
        __syncthreads();
        sh[t] += x;
    }
    __syncthreads();
    int excl = sh[t] - v;
    if (i < n) {
        int rp = g_boff[blockIdx.x] + excl;
        g_rowptr[i] = rp;
        g_dinv[i] = rsqrtf((float)v);
        // self-loop edge first (deterministic slot)
        g_csr_src[rp] = i;
        g_woff[i] = rp + 1;
        if (i == n - 1) g_rowptr[n] = rp + v;
    }
}

__global__ void k_scatter(const int* __restrict__ src, const int* __restrict__ dst, int e) {
    int i = blockIdx.x * blockDim.x + threadIdx.x;
    if (i >= e) return;
    int d = dst[i];
    int pos = atomicAdd(&g_woff[d], 1);
    g_csr_src[pos] = src[i];
}

// ---------------- dual tensor-core GEMM ---------------------------------
// Two independent problems in one launch (blockIdx < nb0 -> problem 0).
// H[r, co:co+64] = fp16( dinv[r] * (A[r,:K] @ W[K,64]) ), row stride 128 halfs.
// bf16 hi/lo 3-split on mma.m16n8k16 (hi*hi + hi*lo + lo*hi), fp32 accumulate.
__global__ void __launch_bounds__(256) k_gemm_dual(
        const float* __restrict__ A0, const float* __restrict__ W0, int K0, int co0,
        int nb0,
        const float* __restrict__ A1, const float* __restrict__ W1, int K1, int co1,
        __half* __restrict__ Ch, int n) {
    constexpr int BM = 128, BK = 16, AST = 12, WST = 12;  // strides in 32-bit words
    __shared__ unsigned Ah[BM][AST];
    __shared__ unsigned Al[BM][AST];
    __shared__ unsigned Wh[64][WST];
    __shared__ unsigned Wl[64][WST];

    const float* A; const float* W; int K; int m0; int co;
    if (blockIdx.x < nb0) { A = A0; W = W0; K = K0; co = co0; m0 = blockIdx.x * BM; }
    else                  { A = A1; W = W1; K = K1; co = co1; m0 = (blockIdx.x - nb0) * BM; }

    int tid  = threadIdx.x;
    int warp = tid >> 5;
    int lane = tid & 31;
    int q = lane & 3;        // threadID_in_group
    int g = lane >> 2;       // groupID
    int rg = warp & 3;       // row-group: rows rg*32 .. rg*32+31
    int cg = warp >> 2;      // col-group: cols cg*32 .. cg*32+31
    int mrow = rg * 32;
    int ncol = cg * 32;

    float acc[2][4][4];
    #pragma unroll
    for (int mt = 0; mt < 2; ++mt)
        #pragma unroll
        for (int nt = 0; nt < 4; ++nt)
            #pragma unroll
            for (int j = 0; j < 4; ++j) acc[mt][nt][j] = 0.f;

    // staging coords
    int a_row = tid >> 2;                // 0..63 (+64 on second pass)
    int a_c4  = (tid & 3) * 4;           // k offset 0,4,8,12
    int w_col = tid & 63;                // 0..63
    int w_kb  = (tid >> 6) * 4;          // 0,4,8,12

    for (int k0 = 0; k0 < K; k0 += BK) {
        // --- stage A tile: 128x16, hi via PRMT truncation, lo via RN bf16 ---
        #pragma unroll
        for (int r = 0; r < 2; ++r) {
            int row = a_row + r * 64;
            int gr  = m0 + row;
            float4 v = make_float4(0.f, 0.f, 0.f, 0.f);
            if (gr < n) v = *reinterpret_cast<const float4*>(&A[(size_t)gr * K + k0 + a_c4]);
            unsigned bx = __float_as_uint(v.x), by = __float_as_uint(v.y);
            unsigned bz = __float_as_uint(v.z), bw = __float_as_uint(v.w);
            Ah[row][(a_c4 >> 1)    ] = prmt_hipack(bx, by);
            Ah[row][(a_c4 >> 1) + 1] = prmt_hipack(bz, bw);
            Al[row][(a_c4 >> 1)    ] = bf16x2_rn(v.x - trunc_bf16f(v.x), v.y - trunc_bf16f(v.y));
            Al[row][(a_c4 >> 1) + 1] = bf16x2_rn(v.z - trunc_bf16f(v.z), v.w - trunc_bf16f(v.w));
        }
        // --- stage W tile: 16x64, each thread 4 consecutive k for one col ---
        {
            float w0 = W[(size_t)(k0 + w_kb + 0) * 64 + w_col];
            float w1 = W[(size_t)(k0 + w_kb + 1) * 64 + w_col];
            float w2 = W[(size_t)(k0 + w_kb + 2) * 64 + w_col];
            float w3 = W[(size_t)(k0 + w_kb + 3) * 64 + w_col];
            Wh[w_col][(w_kb >> 1)    ] = prmt_hipack(__float_as_uint(w0), __float_as_uint(w1));
            Wh[w_col][(w_kb >> 1) + 1] = prmt_hipack(__float_as_uint(w2), __float_as_uint(w3));
            Wl[w_col][(w_kb >> 1)    ] = bf16x2_rn(w0 - trunc_bf16f(w0), w1 - trunc_bf16f(w1));
            Wl[w_col][(w_kb >> 1) + 1] = bf16x2_rn(w2 - trunc_bf16f(w2), w3 - trunc_bf16f(w3));
        }
        __syncthreads();

        // --- fragment loads + MMAs (one 16-k step) ---
        unsigned ah[2][4], al[2][4];
        #pragma unroll
        for (int mt = 0; mt < 2; ++mt) {
            int rbase = mrow + mt * 16;
            ah[mt][0] = Ah[rbase + g    ][q    ];
            ah[mt][1] = Ah[rbase + g + 8][q    ];
            ah[mt][2] = Ah[rbase + g    ][q + 4];
            ah[mt][3] = Ah[rbase + g + 8][q + 4];
            al[mt][0] = Al[rbase + g    ][q    ];
            al[mt][1] = Al[rbase + g + 8][q    ];
            al[mt][2] = Al[rbase + g    ][q + 4];
            al[mt][3] = Al[rbase + g + 8][q + 4];
        }
        #pragma unroll
        for (int nt = 0; nt < 4; ++nt) {
            int col = ncol + nt * 8 + g;
            unsigned bh[2], bl[2];
            bh[0] = Wh[col][q];
            bh[1] = Wh[col][q + 4];
            bl[0] = Wl[col][q];
            bl[1] = Wl[col][q + 4];
            #pragma unroll
            for (int mt = 0; mt < 2; ++mt) {
                mma_bf16(acc[mt][nt], ah[mt], bh);
                mma_bf16(acc[mt][nt], ah[mt], bl);
                mma_bf16(acc[mt][nt], al[mt], bh);
            }
        }
        __syncthreads();
    }

    // epilogue: scale rows by dinv, convert fp16, write half2 fragments
    #pragma unroll
    for (int mt = 0; mt < 2; ++mt) {
        int r0 = m0 + mrow + mt * 16 + g;
        int r1 = r0 + 8;
        float d0 = (r0 < n) ? g_dinv[r0] : 0.f;
        float d1 = (r1 < n) ? g_dinv[r1] : 0.f;
        #pragma unroll
        for (int nt = 0; nt < 4; ++nt) {
            int col = co + ncol + nt * 8 + q * 2;
            if (r0 < n)
                *reinterpret_cast<__half2*>(&Ch[(size_t)r0 * 128 + col]) =
                    __floats2half2_rn(acc[mt][nt][0] * d0, acc[mt][nt][1] * d0);
            if (r1 < n)
                *reinterpret_cast<__half2*>(&Ch[(size_t)r1 * 128 + col]) =
                    __floats2half2_rn(acc[mt][nt][2] * d1, acc[mt][nt][3] * d1);
        }
    }
}

// ---------------- agg helper: per-lane 4-col fp32 accumulation over edges -----
// H row = 128 fp16 = 256 B = 32 uint2; lane covers cols 4*lane..4*lane+3
// -> index = s*32 + lane (one LDG.64 per edge per lane, fully coalesced).
struct Acc4 { float v[4]; };
__device__ __forceinline__ void acc_edge(Acc4& a, const uint2* __restrict__ hp,
                                         int s, int lane) {
    uint2 u = hp[(size_t)s * 32 + lane];
    __half2 h0 = *reinterpret_cast<__half2*>(&u.x);
    __half2 h1 = *reinterpret_cast<__half2*>(&u.y);
    float2 f0 = __half22float2(h0);
    float2 f1 = __half22float2(h1);
    a.v[0] += f0.x; a.v[1] += f0.y; a.v[2] += f1.x; a.v[3] += f1.y;
}

// ---------------- agg1: both branches, bias+ELU, fp32 out (feeds gemm2) -------
__global__ void __launch_bounds__(256) k_agg1(
        const __half* __restrict__ H,
        const float* __restrict__ b0, const float* __restrict__ b1,
        float* __restrict__ Xa, float* __restrict__ Xb, int n) {
    int node = (blockIdx.x * blockDim.x + threadIdx.x) >> 5;
    int lane = threadIdx.x & 31;
    if (node >= n) return;
    const uint2* hp = reinterpret_cast<const uint2*>(H);
    int start = g_rowptr[node];
    int end   = g_rowptr[node + 1];
    Acc4 a; a.v[0] = a.v[1] = a.v[2] = a.v[3] = 0.f;
    int j = start;
    for (; j + 4 <= end; j += 4) {
        int s0 = g_csr_src[j];
        int s1 = g_csr_src[j + 1];
        int s2 = g_csr_src[j + 2];
        int s3 = g_csr_src[j + 3];
        acc_edge(a, hp, s0, lane);
        acc_edge(a, hp, s1, lane);
        acc_edge(a, hp, s2, lane);
        acc_edge(a, hp, s3, lane);
    }
    for (; j < end; ++j) acc_edge(a, hp, g_csr_src[j], lane);

    float dd = g_dinv[node];
    float4 bb = (lane < 16)
        ? reinterpret_cast<const float4*>(b0)[lane]
        : reinterpret_cast<const float4*>(b1)[lane - 16];
    float4 r;
    r.x = a.v[0] * dd + bb.x;
    r.y = a.v[1] * dd + bb.y;
    r.z = a.v[2] * dd + bb.z;
    r.w = a.v[3] * dd + bb.w;
    r.x = r.x > 0.f ? r.x : expm1f(r.x);
    r.y = r.y > 0.f ? r.y : expm1f(r.y);
    r.z = r.z > 0.f ? r.z : expm1f(r.z);
    r.w = r.w > 0.f ? r.w : expm1f(r.w);
    if (lane < 16)
        reinterpret_cast<float4*>(&Xa[(size_t)node * 64])[lane] = r;
    else
        reinterpret_cast<float4*>(&Xb[(size_t)node * 64])[lane - 16] = r;
}

// ---------------- agg2 + classifier: out[node,4] directly ---------------------
__global__ void __launch_bounds__(256) k_agg2_final(
        const __half* __restrict__ H,
        const float* __restrict__ b0, const float* __restrict__ b1,
        const float* __restrict__ Wfc, const float* __restrict__ bfc,
        float* __restrict__ out, int n) {
    __shared__ float4 ws[128];   // Wfc rows: 128 x 4
    for (int i = threadIdx.x; i < 128; i += 256)
        ws[i] = reinterpret_cast<const float4*>(Wfc)[i];
    __syncthreads();

    int node = (blockIdx.x * blockDim.x + threadIdx.x) >> 5;
    int lane = threadIdx.x & 31;
    if (node >= n) return;
    const uint2* hp = reinterpret_cast<const uint2*>(H);
    int start = g_rowptr[node];
    int end   = g_rowptr[node + 1];
    Acc4 a; a.v[0] = a.v[1] = a.v[2] = a.v[3] = 0.f;
    int j = start;
    for (; j + 4 <= end; j += 4) {
        int s0 = g_csr_src[j];
        int s1 = g_csr_src[j + 1];
        int s2 = g_csr_src[j + 2];
        int s3 = g_csr_src[j + 3];
        acc_edge(a, hp, s0, lane);
        acc_edge(a, hp, s1, lane);
        acc_edge(a, hp, s2, lane);
        acc_edge(a, hp, s3, lane);
    }
    for (; j < end; ++j) acc_edge(a, hp, g_csr_src[j], lane);

    float dd = g_dinv[node];
    float4 bb = (lane < 16)
        ? reinterpret_cast<const float4*>(b0)[lane]
        : reinterpret_cast<const float4*>(b1)[lane - 16];
    float x0 = a.v[0] * dd + bb.x;
    float x1 = a.v[1] * dd + bb.y;
    float x2 = a.v[2] * dd + bb.z;
    float x3 = a.v[3] * dd + bb.w;
    x0 = x0 > 0.f ? x0 : expm1f(x0);
    x1 = x1 > 0.f ? x1 : expm1f(x1);
    x2 = x2 > 0.f ? x2 : expm1f(x2);
    x3 = x3 > 0.f ? x3 : expm1f(x3);

    // classifier: feature index of x_k is 4*lane + k (concat layout matches)
    float4 w0 = ws[4 * lane + 0];
    float4 w1 = ws[4 * lane + 1];
    float4 w2 = ws[4 * lane + 2];
    float4 w3 = ws[4 * lane + 3];
    float4 p;
    p.x = x0 * w0.x + x1 * w1.x + x2 * w2.x + x3 * w3.x;
    p.y = x0 * w0.y + x1 * w1.y + x2 * w2.y + x3 * w3.y;
    p.z = x0 * w0.z + x1 * w1.z + x2 * w2.z + x3 * w3.z;
    p.w = x0 * w0.w + x1 * w1.w + x2 * w2.w + x3 * w3.w;
    #pragma unroll
    for (int off = 16; off; off >>= 1) {
        p.x += __shfl_xor_sync(0xffffffff, p.x, off);
        p.y += __shfl_xor_sync(0xffffffff, p.y, off);
        p.z += __shfl_xor_sync(0xffffffff, p.z, off);
        p.w += __shfl_xor_sync(0xffffffff, p.w, off);
    }
    if (lane == 0) {
        float4 bf = *reinterpret_cast<const float4*>(bfc);
        p.x += bf.x; p.y += bf.y; p.z += bf.z; p.w += bf.w;
        reinterpret_cast<float4*>(out)[node] = p;
    }
}

// ---------------- host launch ----------------
extern "C" void kernel_launch(void* const* d_in, const int* in_sizes, int n_in,
                              void* d_out, int out_size) {
    const float* x1  = (const float*)d_in[0];
    const float* x2  = (const float*)d_in[1];
    const int*   ei  = (const int*)d_in[2];
    const float* W1a = (const float*)d_in[3];
    const float* b1a = (const float*)d_in[4];
    const float* W2a = (const float*)d_in[5];
    const float* b2a = (const float*)d_in[6];
    const float* W1b = (const float*)d_in[7];
    const float* b1b = (const float*)d_in[8];
    const float* W2b = (const float*)d_in[9];
    const float* b2b = (const float*)d_in[10];
    const float* Wfc = (const float*)d_in[11];
    const float* bfc = (const float*)d_in[12];
    float* out = (float*)d_out;

    int n = in_sizes[0] / 512;   // 100000
    int e = in_sizes[2] / 2;     // 1600000
    const int* srcA = ei;
    const int* dstA = ei + e;

    __half* pH;
    float *pXa, *pXb;
    cudaGetSymbolAddress((void**)&pH,  g_Hh);
    cudaGetSymbolAddress((void**)&pXa, g_Xa);
    cudaGetSymbolAddress((void**)&pXb, g_Xb);

    int nblk = (n + 255) / 256;

    // graph build
    k_init_cnt<<<(n + 255) / 256, 256>>>(n);
    k_count<<<(e + 255) / 256, 256>>>(dstA, e);
    k_blocksum<<<nblk, 256>>>(n);
    k_topscan<<<1, 512>>>(nblk);
    k_scanwrite<<<nblk, 256>>>(n);
    k_scatter<<<(e + 255) / 256, 256>>>(srcA, dstA, e);

    int nb = (n + 127) / 128;                       // 782
    int node_grid = (n * 32 + 255) / 256;           // one warp per node

    // layer 1 (both branches fused; outputs interleaved fp16 [node][128])
    k_gemm_dual<<<2 * nb, 256>>>(x1, W1a, 512, 0, nb, x2, W1b, 256, 64, pH, n);
    k_agg1<<<node_grid, 256>>>(pH, b1a, b1b, pXa, pXb, n);

    // layer 2 (both branches fused)
    k_gemm_dual<<<2 * nb, 256>>>(pXa, W2a, 64, 0, nb, pXb, W2b, 64, 64, pH, n);
    k_agg2_final<<<node_grid, 256>>>(pH, b2a, b2b, Wfc, bfc, out, n);
}